// round 13
// baseline (speedup 1.0000x reference)
#include <cuda_runtime.h>
#include <cuda_bf16.h>

#define EPS 1e-5f

// Scratch (device globals: allocation-free)
__device__ float g_a[256 * 32];     // a = x@W1 + b1
__device__ float g_s[256];          // row sums of a
__device__ float g_q[256];          // row sums of a^2
__device__ float g_U[256 * 1024];   // U[i][o*32+e] = sum_d a[i,d]*gamma[d*32+e]*W2[(d*32+e)*32+o]
__device__ float g_c[32];           // c[o] = sum_k gamma[k]*W2[k,o]
__device__ float g_t[32];           // t[o] = sum_k beta[k]*W2[k,o] + b2[o]

// ---- f32x2 packed helpers (Blackwell) ----
#define FMA_F32X2(acc, a, b) \
    asm("fma.rn.f32x2 %0, %1, %2, %3;" : "=l"(acc) : "l"(a), "l"(b), "l"(acc))
#define PACK2(out, lo, hi) \
    asm("mov.b64 %0, {%1, %2};" : "=l"(out) : "f"(lo), "f"(hi))
#define DUP2(out, v) \
    asm("mov.b64 %0, {%1, %1};" : "=l"(out) : "f"(v))
#define UNPACK2(lo, hi, in) \
    asm("mov.b64 {%0, %1}, %2;" : "=f"(lo), "=f"(hi) : "l"(in))

// ---------------------------------------------------------------------------
// kA: blocks 0..255: it = bx>>2 (64 i-tiles of 4 rows), ct = bx&3 (256-col tile)
//   Phase 1: a = x@W1 + b1 for 4 rows (publish a/s/q when ct==0)
//   Phase 2: per-thread g[d] (coalesced LDG), U via f32x2 over packed row-pairs
//   Phase 3: smem transpose -> store U as [i][o*32+e] (coalesced STG.128)
// block 256: c[o], t[o].
// ---------------------------------------------------------------------------
__global__ __launch_bounds__(256) void kA(const float* __restrict__ x,
                                          const float* __restrict__ W1,
                                          const float* __restrict__ b1,
                                          const float* __restrict__ gamma,
                                          const float* __restrict__ beta,
                                          const float* __restrict__ W2,
                                          const float* __restrict__ b2) {
    int bx = blockIdx.x;
    int tid = threadIdx.x;

    if (bx == 256) {
        __shared__ float rc[8][32], rt[8][32];
        int o = tid & 31, grp = tid >> 5;
        float pc = 0.f, pt = 0.f;
        int k0i = grp * 128;
#pragma unroll 8
        for (int k = k0i; k < k0i + 128; k++) {
            float w = W2[k * 32 + o];
            pc += gamma[k] * w;
            pt += beta[k] * w;
        }
        rc[grp][o] = pc;
        rt[grp][o] = pt;
        __syncthreads();
        if (tid < 32) {
            float cc = 0.f, tt = b2[o];
#pragma unroll
            for (int g = 0; g < 8; g++) { cc += rc[g][o]; tt += rt[g][o]; }
            g_c[o] = cc;
            g_t[o] = tt;
        }
        return;
    }

    int it = bx >> 2, ct = bx & 3;
    int i0 = it * 4;

    __shared__ __align__(16) float xs[4 * 256];               // 4 KB
    __shared__ float red[8][4][32];                           // 4 KB
    __shared__ float aa[4][32];
    __shared__ __align__(16) unsigned long long as2[2][32];   // packed row pairs
    __shared__ __align__(16) float T[4][32 * 33];             // 16.5 KB transpose buf

    // x rows i0..i0+3 (1024 floats)
    {
        const float4* xp = (const float4*)(x + i0 * 256);
        ((float4*)xs)[tid] = xp[tid];
    }
    __syncthreads();

    int h = tid & 31, grp = tid >> 5;
    {
        float acc[4] = {0.f, 0.f, 0.f, 0.f};
#pragma unroll
        for (int cc = 0; cc < 8; cc++) {
            int c = grp * 32 + cc * 4;
            float w0 = W1[(c + 0) * 32 + h];
            float w1 = W1[(c + 1) * 32 + h];
            float w2 = W1[(c + 2) * 32 + h];
            float w3 = W1[(c + 3) * 32 + h];
#pragma unroll
            for (int r = 0; r < 4; r++) {
                float4 xv = *(const float4*)&xs[r * 256 + c];
                acc[r] += xv.x * w0 + xv.y * w1 + xv.z * w2 + xv.w * w3;
            }
        }
#pragma unroll
        for (int r = 0; r < 4; r++) red[grp][r][h] = acc[r];
    }
    __syncthreads();

    if (tid < 128) {
        int r = tid >> 5;
        float a = b1[h];
#pragma unroll
        for (int g = 0; g < 8; g++) a += red[g][r][h];
        aa[r][h] = a;
        if (ct == 0) g_a[(i0 + r) * 32 + h] = a;
        float s = a, q = a * a;
#pragma unroll
        for (int off = 16; off; off >>= 1) {
            s += __shfl_down_sync(0xffffffffu, s, off);
            q += __shfl_down_sync(0xffffffffu, q, off);
        }
        if (ct == 0 && h == 0) { g_s[i0 + r] = s; g_q[i0 + r] = q; }
    }
    __syncthreads();
    if (tid < 64) {
        int r2 = tid >> 5, dd = tid & 31;
        unsigned long long v;
        PACK2(v, aa[2 * r2][dd], aa[2 * r2 + 1][dd]);
        as2[r2][dd] = v;
    }
    __syncthreads();

    // U compute: col = ct*256 + tid, layout-in col = e*32+o
    {
        int col = ct * 256 + tid;
        int e = col >> 5, o = col & 31;
        float g[32];
#pragma unroll
        for (int d = 0; d < 32; d++)
            g[d] = gamma[d * 32 + e] * W2[(d * 32 + e) * 32 + o];

        unsigned long long acc2[2] = {0ull, 0ull};
#pragma unroll
        for (int d = 0; d < 32; d++) {
            unsigned long long gd;
            DUP2(gd, g[d]);
            FMA_F32X2(acc2[0], as2[0][d], gd);
            FMA_F32X2(acc2[1], as2[1][d], gd);
        }
        // transpose stage: T[r][o*33 + e]  (lanes o consecutive -> conflict-free)
#pragma unroll
        for (int r2 = 0; r2 < 2; r2++) {
            float a0, a1;
            UNPACK2(a0, a1, acc2[r2]);
            T[2 * r2][o * 33 + e]     = a0;
            T[2 * r2 + 1][o * 33 + e] = a1;
        }
    }
    __syncthreads();

    // store U[i][o*32+e], coalesced STG.128; this block owns cols ct*256..+255
    // which are e in [ct*8, ct*8+8) for all o -> target float4s: e4 in [ct*2, ct*2+2)
#pragma unroll
    for (int k = 0; k < 4; k++) {
        int f = tid + k * 256;              // 1024 float4 tasks
        int r = f >> 8, rem = f & 255;
        int o = rem >> 3, e4l = rem & 7;    // e4l in [0,8) -> local e4 within... 
        // this block covers 8 e-values: e = ct*8 + (e4l selects which 4? we have 8 e)
        // 8 e per o -> 2 float4s per o; map e4l: 0..7 -> (pair = e4l&1, rep = e4l>>1)
        // simpler: tasks = 4 rows * 32 o * 2 float4 = 256 per row -> f covers 1024? 
        // total float4s this block = 4r*32o*2 = 256. Use only k<1 with 256 threads.
        if (k == 0) {
            int ff = tid;                   // 256 tasks
            int rr = ff >> 6, rrem = ff & 63;
            int oo = rrem >> 1, p = rrem & 1;
            int e0 = ct * 8 + p * 4;
            float4 v;
            v.x = T[rr][oo * 33 + e0 + 0];
            v.y = T[rr][oo * 33 + e0 + 1];
            v.z = T[rr][oo * 33 + e0 + 2];
            v.w = T[rr][oo * 33 + e0 + 3];
            *(float4*)&g_U[(size_t)(i0 + rr) * 1024 + oo * 32 + e0] = v;
        }
    }
}

// ---------------------------------------------------------------------------
// k3: out[i,j,o] = P_ij*(sum_e U[i,e,o]*a[j,e]) + (t[o] - Q_ij*c[o])
// Grid (8 j-chunks of 32, 64 i-tiles of 4), 128 thr = 32 o x 4 jslot.
// U staged [i][o][e] pitch-36 (quarter-warp conflict-free LDS.128).
// Per ec: 4 u LDS.128 + 8 b LDS.128 (broadcast) front-batched, 16 DUP, 64 FFMA2.
// ---------------------------------------------------------------------------
__global__ __launch_bounds__(128, 4) void k3(float* __restrict__ out) {
    __shared__ __align__(16) float Us[4][32 * 36];             // 18 KB
    __shared__ __align__(16) unsigned long long ajp[16][32];   // 4 KB
    __shared__ __align__(16) float pq[4][16][4];               // 1 KB

    int tid = threadIdx.x;
    int j0 = blockIdx.x * 32, i0 = blockIdx.y * 4;

    // stage U (gmem [i][o*32+e] -> smem [i][o*36+e]); STS.128 conflict-free
    {
        const float4* up = (const float4*)(g_U + (size_t)i0 * 1024);
#pragma unroll
        for (int k = 0; k < 8; k++) {
            int f = tid + k * 128;          // 1024 float4s
            float4 v = up[f];
            int i = f >> 8, rem = f & 255;
            int o = rem >> 3, e4 = rem & 7;
            *(float4*)&Us[i][o * 36 + e4 * 4] = v;
        }
    }
#pragma unroll
    for (int k = 0; k < 4; k++) {
        int idx = tid + k * 128;
        int jp = idx >> 5, e = idx & 31;
        float a0 = g_a[(j0 + 2 * jp) * 32 + e];
        float a1 = g_a[(j0 + 2 * jp + 1) * 32 + e];
        unsigned long long v;
        PACK2(v, a0, a1);
        ajp[jp][e] = v;
    }
    if (tid < 64) {
        int il = tid >> 4, jp = tid & 15;
        const float inv = 1.0f / 1024.0f;
        float si = g_s[i0 + il] * inv, qi = g_q[i0 + il] * inv;
        float4 v;
        int j = j0 + 2 * jp;
        float mu = si * g_s[j];
        float var = qi * g_q[j] - mu * mu;
        float r = rsqrtf(var + EPS);
        v.x = r; v.z = r * mu;
        j++;
        mu = si * g_s[j];
        var = qi * g_q[j] - mu * mu;
        r = rsqrtf(var + EPS);
        v.y = r; v.w = r * mu;
        *(float4*)&pq[il][jp][0] = v;
    }
    __syncthreads();

    int o = tid & 31, jslot = tid >> 5;
    float co = g_c[o], to = g_t[o];

    unsigned long long acc[4][4];
#pragma unroll
    for (int i = 0; i < 4; i++)
#pragma unroll
        for (int jp = 0; jp < 4; jp++) acc[i][jp] = 0ull;

#pragma unroll
    for (int ec = 0; ec < 8; ec++) {
        // front-batched loads
        float4 uv[4];
#pragma unroll
        for (int i = 0; i < 4; i++)
            uv[i] = *(const float4*)&Us[i][o * 36 + ec * 4];
        unsigned long long bb[4][4];
#pragma unroll
        for (int jp = 0; jp < 4; jp++) {
            const ulonglong2* bp = (const ulonglong2*)&ajp[jslot * 4 + jp][ec * 4];
            ulonglong2 b01 = bp[0], b23 = bp[1];
            bb[jp][0] = b01.x; bb[jp][1] = b01.y;
            bb[jp][2] = b23.x; bb[jp][3] = b23.y;
        }
#pragma unroll
        for (int i = 0; i < 4; i++) {
            float ue[4] = {uv[i].x, uv[i].y, uv[i].z, uv[i].w};
#pragma unroll
            for (int e = 0; e < 4; e++) {
                unsigned long long uu;
                DUP2(uu, ue[e]);
                FMA_F32X2(acc[i][0], uu, bb[0][e]);
                FMA_F32X2(acc[i][1], uu, bb[1][e]);
                FMA_F32X2(acc[i][2], uu, bb[2][e]);
                FMA_F32X2(acc[i][3], uu, bb[3][e]);
            }
        }
    }

#pragma unroll
    for (int i = 0; i < 4; i++) {
        float* op = out + ((size_t)(i0 + i) * 256 + j0 + jslot * 8) * 32 + o;
#pragma unroll
        for (int jp = 0; jp < 4; jp++) {
            float4 v = *(const float4*)&pq[i][jslot * 4 + jp][0];
            float a0, a1;
            UNPACK2(a0, a1, acc[i][jp]);
            op[(size_t)(2 * jp) * 32]     = v.x * a0 + (to - v.z * co);
            op[(size_t)(2 * jp + 1) * 32] = v.y * a1 + (to - v.w * co);
        }
    }
}

extern "C" void kernel_launch(void* const* d_in, const int* in_sizes, int n_in,
                              void* d_out, int out_size) {
    const float* x     = (const float*)d_in[0];
    const float* W1    = (const float*)d_in[1];
    const float* b1    = (const float*)d_in[2];
    const float* gamma = (const float*)d_in[3];
    const float* beta  = (const float*)d_in[4];
    const float* W2    = (const float*)d_in[5];
    const float* b2    = (const float*)d_in[6];
    float* out = (float*)d_out;

    kA<<<257, 256>>>(x, W1, b1, gamma, beta, W2, b2);
    k3<<<dim3(8, 64), 128>>>(out);
}